// round 6
// baseline (speedup 1.0000x reference)
#include <cuda_runtime.h>
#include <math.h>

#define RES      256
#define NTRI     1000
#define NBATCH   2
#define EPSF     1e-8f
#define NPIX     (RES * RES)
#define NPAIR    (NPIX / 2)          // y-pairs packed in u64
#define SCALEF   2097152.0f          // 2^21
#define INVSCALE (1.0f / 2097152.0f)
#define YSPLIT   4                   // scatter blocks per triangle
#define NREP     8                   // accumulator replicas (contention relief)

// replica accumulators: low 32 = y even, high 32 = y odd.
// layout: ((rep*NBATCH)+b)*NPAIR + x*128 + (y>>1)
// Zero-initialized at module load; finalize_kernel re-zeros every launch.
__device__ unsigned long long g_accum[NREP * NBATCH * NPAIR];

struct Coef { float A0,B0,C0, A1,B1,C1, A2,B2,C2; };

// exact score evaluation — the SAME formula everywhere
__device__ __forceinline__ float eval_s(const Coef& c, float fx, float fy)
{
    float t0 = fmaxf(fmaf(c.C0, fy, fmaf(c.B0, fx, c.A0)), 0.0f);
    float t1 = fmaxf(fmaf(c.C1, fy, fmaf(c.B1, fx, c.A1)), 0.0f);
    float t2 = fmaxf(fmaf(c.C2, fy, fmaf(c.B2, fx, c.A2)), 0.0f);
    return t0 * t1 * t2;
}

// (5,4) continued-fraction Pade tanh, err <= ~2.4e-5 on [0, 1.05]; branch-free
__device__ __forceinline__ float tanh_pade(float x)
{
    float t   = x * x;
    float num = fmaf(t, fmaf(t, 1.0f, 105.0f), 945.0f);
    float den = fmaf(t, fmaf(t, 15.0f, 420.0f), 945.0f);
    return x * __fdividef(num, den);
}

// positive-interval [lo,hi] of row fy (normalized coeffs); empty -> lo > hi
__device__ __forceinline__ void row_iv(const Coef& n, float fy, float& lo, float& hi)
{
    float a0 = fmaf(n.C0, fy, n.A0);
    float a1 = fmaf(n.C1, fy, n.A1);
    float a2 = fmaf(n.C2, fy, n.A2);
    lo = -1e30f; hi = 1e30f;
    if (n.B0 >  1e-25f)      lo = fmaxf(lo, -__fdividef(a0, n.B0));
    else if (n.B0 < -1e-25f) hi = fminf(hi, -__fdividef(a0, n.B0));
    else if (a0 <= 0.0f)   { lo = 1e30f; hi = -1e30f; return; }
    if (n.B1 >  1e-25f)      lo = fmaxf(lo, -__fdividef(a1, n.B1));
    else if (n.B1 < -1e-25f) hi = fminf(hi, -__fdividef(a1, n.B1));
    else if (a1 <= 0.0f)   { lo = 1e30f; hi = -1e30f; return; }
    if (n.B2 >  1e-25f)      lo = fmaxf(lo, -__fdividef(a2, n.B2));
    else if (n.B2 < -1e-25f) hi = fminf(hi, -__fdividef(a2, n.B2));
    else if (a2 <= 0.0f)   { lo = 1e30f; hi = -1e30f; return; }
}

// exact grid max of the clamped product over row y within [bb.x, bb.y]
__device__ float row_max(const Coef& c, const Coef& n, const int4 bb, int y)
{
    const float fy = (float)y;
    float a0 = fmaf(n.C0, fy, n.A0);
    float a1 = fmaf(n.C1, fy, n.A1);
    float a2 = fmaf(n.C2, fy, n.A2);

    float lo = (float)bb.x, hi = (float)bb.y;
    bool ok = true;
    if (n.B0 >  1e-25f)      lo = fmaxf(lo, -__fdividef(a0, n.B0));
    else if (n.B0 < -1e-25f) hi = fminf(hi, -__fdividef(a0, n.B0));
    else                     ok = ok && (a0 > 0.0f);
    if (n.B1 >  1e-25f)      lo = fmaxf(lo, -__fdividef(a1, n.B1));
    else if (n.B1 < -1e-25f) hi = fminf(hi, -__fdividef(a1, n.B1));
    else                     ok = ok && (a1 > 0.0f);
    if (n.B2 >  1e-25f)      lo = fmaxf(lo, -__fdividef(a2, n.B2));
    else if (n.B2 < -1e-25f) hi = fminf(hi, -__fdividef(a2, n.B2));
    else                     ok = ok && (a2 > 0.0f);

    float clo = ceilf(lo), chi = floorf(hi);
    if (!ok || clo > chi) return 0.0f;

    float q2 = 3.0f * n.B0 * n.B1 * n.B2;
    float q1 = 2.0f * (n.B0*n.B1*a2 + n.B0*n.B2*a1 + n.B1*n.B2*a0);
    float q0 = n.B0*a1*a2 + n.B1*a0*a2 + n.B2*a0*a1;

    float xc1 = 0.5f * (clo + chi), xc2 = xc1;
    if (fabsf(q2) > 1e-30f) {
        float disc = fmaf(q1, q1, -4.0f * q2 * q0);
        float sq   = sqrtf(fmaxf(disc, 0.0f));
        float i2   = __fdividef(0.5f, q2);
        xc1 = (-q1 + sq) * i2;
        xc2 = (-q1 - sq) * i2;
    } else if (fabsf(q1) > 1e-30f) {
        xc1 = xc2 = -__fdividef(q0, q1);
    }

    float f1 = floorf(xc1), f2 = floorf(xc2);
    float cand[6] = { clo, chi, f1, f1 + 1.0f, f2, f2 + 1.0f };
    float m = 0.0f;
    #pragma unroll
    for (int i = 0; i < 6; i++) {
        float x = fminf(fmaxf(cand[i], clo), chi);   // NaN-safe
        m = fmaxf(m, eval_s(c, x, fy));
    }
    return m;
}

// ---------------------------------------------------------------------------
// grid = (NBATCH*NTRI, YSPLIT).
// ---------------------------------------------------------------------------
__global__ void __launch_bounds__(256) fused_kernel(const float* __restrict__ meshes,
                                                    const float* __restrict__ K,
                                                    const int*   __restrict__ model_idxs,
                                                    const float* __restrict__ poses)
{
    const int bt  = blockIdx.x;
    const int b   = bt / NTRI;
    const int t   = bt - b * NTRI;
    const int tid = threadIdx.x;

    __shared__ Coef  sC, sN;
    __shared__ int4  sBB;
    __shared__ int   sFlag;
    __shared__ float sMn, sInv;
    __shared__ float swmax[8];

    if (tid == 0) {
        float M[12];
        const float* cam = poses + b * 12;
        #pragma unroll
        for (int r = 0; r < 3; r++)
            #pragma unroll
            for (int cc = 0; cc < 4; cc++) {
                float s = 0.0f;
                #pragma unroll
                for (int k = 0; k < 3; k++)
                    s += K[r * 3 + k] * cam[k * 4 + cc];
                M[r * 4 + cc] = s;
            }

        const float* mesh = meshes + ((size_t)model_idxs[b] * NTRI + t) * 9;
        float vx[3], vy[3];
        #pragma unroll
        for (int j = 0; j < 3; j++) {
            float X = mesh[j*3+0], Y = mesh[j*3+1], Z = mesh[j*3+2];
            float x = M[0]*X + M[1]*Y + M[2] *Z + M[3];
            float y = M[4]*X + M[5]*Y + M[6] *Z + M[7];
            float w = M[8]*X + M[9]*Y + M[10]*Z + M[11];
            float iw = 1.0f / (w + EPSF);
            vx[j] = x * iw;  vy[j] = y * iw;
        }

        const float e0x = vx[1]-vx[0], e0y = vy[1]-vy[0];
        const float e1x = vx[2]-vx[1], e1y = vy[2]-vy[1];
        const float e2x = vx[0]-vx[2], e2y = vy[0]-vy[2];
        const float N = e0x * e2y - e0y * e2x + EPSF;

        Coef c;
        c.A0 = N*(e0x*vy[0]-e0y*vx[0]); c.B0 =  N*e0y; c.C0 = -N*e0x;
        c.A1 = N*(e1x*vy[1]-e1y*vx[1]); c.B1 =  N*e1y; c.C1 = -N*e1x;
        c.A2 = N*(e2x*vy[2]-e2y*vx[2]); c.B2 =  N*e2y; c.C2 = -N*e2x;

        bool inter = true;
        #pragma unroll
        for (int k = 0; k < 4; k++) {
            float cx = (k & 1) ? (float)(RES-1) : 0.0f;
            float cy = (k & 2) ? (float)(RES-1) : 0.0f;
            inter = inter && (fmaf(c.C0, cy, fmaf(c.B0, cx, c.A0)) > 0.0f)
                          && (fmaf(c.C1, cy, fmaf(c.B1, cx, c.A1)) > 0.0f)
                          && (fmaf(c.C2, cy, fmaf(c.B2, cx, c.A2)) > 0.0f);
        }

        float fx0 = fminf(fminf(vx[0],vx[1]),vx[2]) - 1.0f;
        float fx1 = fmaxf(fmaxf(vx[0],vx[1]),vx[2]) + 1.0f;
        float fy0 = fminf(fminf(vy[0],vy[1]),vy[2]) - 1.0f;
        float fy1 = fmaxf(fmaxf(vy[0],vy[1]),vy[2]) + 1.0f;
        bool safe = isfinite(fx0) && isfinite(fx1) && isfinite(fy0) && isfinite(fy1)
                    && fabsf(N) > 1e-6f;
        int4 bb;
        if (safe) {
            int x0 = (fx0 < 0.0f) ? 0 : ((fx0 > (float)(RES-1)) ? RES : (int)fx0);
            int x1 = (fx1 > (float)(RES-1)) ? (RES-1) : ((fx1 < 0.0f) ? -1 : (int)fx1);
            int y0 = (fy0 < 0.0f) ? 0 : ((fy0 > (float)(RES-1)) ? RES : (int)fy0);
            int y1 = (fy1 > (float)(RES-1)) ? (RES-1) : ((fy1 < 0.0f) ? -1 : (int)fy1);
            if (x0 > x1 || y0 > y1) { x0 = RES; x1 = -1; y0 = RES; y1 = -1; }
            bb = make_int4(x0, x1, y0, y1);
        } else {
            bb = make_int4(0, RES-1, 0, RES-1);
        }

        float kap = 0.0f;
        kap = fmaxf(kap, fabsf(c.A0)); kap = fmaxf(kap, 256.0f*fabsf(c.B0)); kap = fmaxf(kap, 256.0f*fabsf(c.C0));
        kap = fmaxf(kap, fabsf(c.A1)); kap = fmaxf(kap, 256.0f*fabsf(c.B1)); kap = fmaxf(kap, 256.0f*fabsf(c.C1));
        kap = fmaxf(kap, fabsf(c.A2)); kap = fmaxf(kap, 256.0f*fabsf(c.B2)); kap = fmaxf(kap, 256.0f*fabsf(c.C2));
        float rk = (kap > 1e-30f) ? (1.0f / kap) : 0.0f;
        Coef nn;
        nn.A0 = c.A0*rk; nn.B0 = c.B0*rk; nn.C0 = c.C0*rk;
        nn.A1 = c.A1*rk; nn.B1 = c.B1*rk; nn.C1 = c.C1*rk;
        nn.A2 = c.A2*rk; nn.B2 = c.B2*rk; nn.C2 = c.C2*rk;

        sC = c; sN = nn; sBB = bb; sFlag = inter ? 1 : 0;
    }
    __syncthreads();

    const Coef c  = sC;
    const Coef n  = sN;
    const int4 bb = sBB;

    // ---- phase 1: analytic per-row max (duplicated across YSPLIT siblings) --
    float mx = 0.0f;
    for (int y = bb.z + tid; y <= bb.w; y += 256)
        mx = fmaxf(mx, row_max(c, n, bb, y));

    #pragma unroll
    for (int o = 16; o > 0; o >>= 1)
        mx = fmaxf(mx, __shfl_xor_sync(0xffffffffu, mx, o));
    if ((tid & 31) == 0) swmax[tid >> 5] = mx;
    __syncthreads();
    if (tid == 0) {
        float rmx = swmax[0];
        #pragma unroll
        for (int i = 1; i < 8; i++) rmx = fmaxf(rmx, swmax[i]);
        float mn = 0.0f;
        if (sFlag) {   // quasi-concave => grid min at an image corner
            const float e = (float)(RES - 1);
            mn = eval_s(c, 0.0f, 0.0f);
            mn = fminf(mn, eval_s(c, e, 0.0f));
            mn = fminf(mn, eval_s(c, 0.0f, e));
            mn = fminf(mn, eval_s(c, e, e));
        }
        sMn  = mn;
        sInv = 1.0f / (rmx - mn + EPSF);
    }
    __syncthreads();

    const float mn  = sMn;
    const float inv = sInv;

    // ---- phase 2: interval scatter into this triangle's replica ------------
    const int wid  = tid >> 5;
    const int lane = tid & 31;
    const int k0 = bb.z >> 1;
    const int k1 = bb.w >> 1;
    const int rep = bt & (NREP - 1);
    unsigned long long* __restrict__ acc =
        g_accum + ((size_t)rep * NBATCH + b) * NPAIR;

    for (int k = k0 + (int)(blockIdx.y * 8 + wid); k <= k1; k += 8 * YSPLIT) {
        const int   y0 = 2 * k, y1 = 2 * k + 1;
        const float fy0 = (float)y0, fy1 = (float)y1;

        float lo0, hi0, lo1, hi1;
        row_iv(n, fy0, lo0, hi0);
        row_iv(n, fy1, lo1, hi1);
        if (y0 < bb.z) { lo0 = 1e30f; hi0 = -1e30f; }
        if (y1 > bb.w) { lo1 = 1e30f; hi1 = -1e30f; }

        float xsf = fmaxf((float)bb.x, ceilf(fminf(lo0, lo1)) - 1.0f);
        float xef = fminf((float)bb.y, floorf(fmaxf(hi0, hi1)) + 1.0f);
        const int xs = (int)xsf;
        const int xe = (int)xef;

        for (int x = xs + lane; x <= xe; x += 32) {
            const float fx = (float)x;
            unsigned int v0 = 0u, v1 = 0u;
            float d0 = eval_s(c, fx, fy0) - mn;
            if (d0 > 0.0f) v0 = __float2uint_rn(tanh_pade(d0 * inv) * SCALEF);
            float d1 = eval_s(c, fx, fy1) - mn;
            if (d1 > 0.0f) v1 = __float2uint_rn(tanh_pade(d1 * inv) * SCALEF);
            unsigned long long p = (unsigned long long)v0
                                 | ((unsigned long long)v1 << 32);
            if (p) atomicAdd(acc + x * (RES / 2) + k, p);
        }
    }
}

// ---------------------------------------------------------------------------
// finalize: sum the NREP replicas per pixel-pair, unpack to float output, and
// reset all replicas to zero for the next graph replay. One thread per pair.
// ---------------------------------------------------------------------------
__global__ void finalize_kernel(float* __restrict__ out)
{
    const int i = blockIdx.x * blockDim.x + threadIdx.x;   // [0, NBATCH*NPAIR)
    if (i >= NBATCH * NPAIR) return;
    const int b = i / NPAIR;
    const int r = i - b * NPAIR;          // r = x*128 + k

    unsigned long long s = 0ull;
    #pragma unroll
    for (int rep = 0; rep < NREP; rep++) {
        unsigned long long* p = g_accum + ((size_t)rep * NBATCH + b) * NPAIR + r;
        s += *p;                           // independent loads -> MLP overlap
        *p = 0ull;
    }

    const int x = r >> 7;
    const int k = r & 127;
    float* o = out + (size_t)b * NPIX + x * RES + 2 * k;
    o[0] = (float)(unsigned int)(s)       * INVSCALE;
    o[1] = (float)(unsigned int)(s >> 32) * INVSCALE;
}

// ---------------------------------------------------------------------------
extern "C" void kernel_launch(void* const* d_in, const int* in_sizes, int n_in,
                              void* d_out, int out_size)
{
    const float* meshes = (const float*)d_in[0];
    const float* K      = (const float*)d_in[1];
    const int*   idxs   = (const int*)  d_in[2];
    const float* poses  = (const float*)d_in[3];
    float*       out    = (float*)d_out;

    dim3 g(NBATCH * NTRI, YSPLIT);
    fused_kernel<<<g, 256>>>(meshes, K, idxs, poses);
    finalize_kernel<<<(NBATCH * NPAIR + 255) / 256, 256>>>(out);
}

// round 8
// speedup vs baseline: 1.1500x; 1.1500x over previous
#include <cuda_runtime.h>
#include <math.h>

#define RES      256
#define NTRI     1000
#define NBATCH   2
#define NBT      (NBATCH * NTRI)
#define EPSF     1e-8f
#define NPIX     (RES * RES)
#define NPAIR    (NPIX / 2)          // y-pairs packed in u64
#define SCALEF   2097152.0f          // 2^21
#define INVSCALE (1.0f / 2097152.0f)
#define YSPLIT   2                   // scatter blocks per triangle

// accumulator: low 32 = y even, high 32 = y odd. addr = b*NPAIR + x*128 + (y>>1)
// Zero at module load; finalize re-zeros every launch.
__device__ unsigned long long g_accum[NBATCH * NPAIR];

// per-(b,t) params: q0={A0,B0,C0,A1} q1={B1,C1,A2,B2} q2={C2,mn,inv,unused}
__device__ float4 g_q[NBT * 3];
__device__ int4   g_bb[NBT];

struct Coef { float A0,B0,C0, A1,B1,C1, A2,B2,C2; };

__device__ __forceinline__ float eval_s(const Coef& c, float fx, float fy)
{
    float t0 = fmaxf(fmaf(c.C0, fy, fmaf(c.B0, fx, c.A0)), 0.0f);
    float t1 = fmaxf(fmaf(c.C1, fy, fmaf(c.B1, fx, c.A1)), 0.0f);
    float t2 = fmaxf(fmaf(c.C2, fy, fmaf(c.B2, fx, c.A2)), 0.0f);
    return t0 * t1 * t2;
}

// (5,4) continued-fraction Pade tanh, err <= ~2.4e-5 on [0, 1.05]
__device__ __forceinline__ float tanh_pade(float x)
{
    float t   = x * x;
    float num = fmaf(t, fmaf(t, 1.0f, 105.0f), 945.0f);
    float den = fmaf(t, fmaf(t, 15.0f, 420.0f), 945.0f);
    return x * __fdividef(num, den);
}

// positive-interval [lo,hi] of row fy; empty -> lo > hi
__device__ __forceinline__ void row_iv(float B0, float B1, float B2,
                                       float r0, float r1, float r2,
                                       float& lo, float& hi)
{
    lo = -1e30f; hi = 1e30f;
    if (B0 >  1e-25f)      lo = fmaxf(lo, -__fdividef(r0, B0));
    else if (B0 < -1e-25f) hi = fminf(hi, -__fdividef(r0, B0));
    else if (r0 <= 0.0f) { lo = 1e30f; hi = -1e30f; return; }
    if (B1 >  1e-25f)      lo = fmaxf(lo, -__fdividef(r1, B1));
    else if (B1 < -1e-25f) hi = fminf(hi, -__fdividef(r1, B1));
    else if (r1 <= 0.0f) { lo = 1e30f; hi = -1e30f; return; }
    if (B2 >  1e-25f)      lo = fmaxf(lo, -__fdividef(r2, B2));
    else if (B2 < -1e-25f) hi = fminf(hi, -__fdividef(r2, B2));
    else if (r2 <= 0.0f) { lo = 1e30f; hi = -1e30f; return; }
}

// exact grid max over row y within [bb.x, bb.y] (log-concave -> candidates)
__device__ float row_max(const Coef& c, const Coef& n, const int4 bb, int y)
{
    const float fy = (float)y;
    float a0 = fmaf(n.C0, fy, n.A0);
    float a1 = fmaf(n.C1, fy, n.A1);
    float a2 = fmaf(n.C2, fy, n.A2);

    float lo = (float)bb.x, hi = (float)bb.y;
    bool ok = true;
    if (n.B0 >  1e-25f)      lo = fmaxf(lo, -__fdividef(a0, n.B0));
    else if (n.B0 < -1e-25f) hi = fminf(hi, -__fdividef(a0, n.B0));
    else                     ok = ok && (a0 > 0.0f);
    if (n.B1 >  1e-25f)      lo = fmaxf(lo, -__fdividef(a1, n.B1));
    else if (n.B1 < -1e-25f) hi = fminf(hi, -__fdividef(a1, n.B1));
    else                     ok = ok && (a1 > 0.0f);
    if (n.B2 >  1e-25f)      lo = fmaxf(lo, -__fdividef(a2, n.B2));
    else if (n.B2 < -1e-25f) hi = fminf(hi, -__fdividef(a2, n.B2));
    else                     ok = ok && (a2 > 0.0f);

    float clo = ceilf(lo), chi = floorf(hi);
    if (!ok || clo > chi) return 0.0f;

    float q2 = 3.0f * n.B0 * n.B1 * n.B2;
    float q1 = 2.0f * (n.B0*n.B1*a2 + n.B0*n.B2*a1 + n.B1*n.B2*a0);
    float q0 = n.B0*a1*a2 + n.B1*a0*a2 + n.B2*a0*a1;

    float xc1 = 0.5f * (clo + chi), xc2 = xc1;
    if (fabsf(q2) > 1e-30f) {
        float disc = fmaf(q1, q1, -4.0f * q2 * q0);
        float sq   = sqrtf(fmaxf(disc, 0.0f));
        float i2   = __fdividef(0.5f, q2);
        xc1 = (-q1 + sq) * i2;
        xc2 = (-q1 - sq) * i2;
    } else if (fabsf(q1) > 1e-30f) {
        xc1 = xc2 = -__fdividef(q0, q1);
    }

    float f1 = floorf(xc1), f2 = floorf(xc2);
    float cand[6] = { clo, chi, f1, f1 + 1.0f, f2, f2 + 1.0f };
    float m = 0.0f;
    #pragma unroll
    for (int i = 0; i < 6; i++) {
        float x = fminf(fmaxf(cand[i], clo), chi);   // NaN-safe
        m = fmaxf(m, eval_s(c, x, fy));
    }
    return m;
}

// ---------------------------------------------------------------------------
// Kernel 1: one warp per (b,t). All lanes redundantly compute coefficients
// (broadcast loads, no serial section), then split the analytic row-max.
// ---------------------------------------------------------------------------
__global__ void __launch_bounds__(256) setup_kernel(const float* __restrict__ meshes,
                                                    const float* __restrict__ K,
                                                    const int*   __restrict__ model_idxs,
                                                    const float* __restrict__ poses)
{
    const int bt = (blockIdx.x * blockDim.x + threadIdx.x) >> 5;
    if (bt >= NBT) return;
    const int lane = threadIdx.x & 31;
    const int b = bt / NTRI;
    const int t = bt - b * NTRI;

    float M[12];
    const float* cam = poses + b * 12;
    #pragma unroll
    for (int r = 0; r < 3; r++)
        #pragma unroll
        for (int cc = 0; cc < 4; cc++) {
            float s = 0.0f;
            #pragma unroll
            for (int k = 0; k < 3; k++)
                s += K[r * 3 + k] * cam[k * 4 + cc];
            M[r * 4 + cc] = s;
        }

    const float* mesh = meshes + ((size_t)model_idxs[b] * NTRI + t) * 9;
    float vx[3], vy[3];
    #pragma unroll
    for (int j = 0; j < 3; j++) {
        float X = mesh[j*3+0], Y = mesh[j*3+1], Z = mesh[j*3+2];
        float x = M[0]*X + M[1]*Y + M[2] *Z + M[3];
        float y = M[4]*X + M[5]*Y + M[6] *Z + M[7];
        float w = M[8]*X + M[9]*Y + M[10]*Z + M[11];
        float iw = 1.0f / (w + EPSF);
        vx[j] = x * iw;  vy[j] = y * iw;
    }

    const float e0x = vx[1]-vx[0], e0y = vy[1]-vy[0];
    const float e1x = vx[2]-vx[1], e1y = vy[2]-vy[1];
    const float e2x = vx[0]-vx[2], e2y = vy[0]-vy[2];
    const float N = e0x * e2y - e0y * e2x + EPSF;

    Coef c;
    c.A0 = N*(e0x*vy[0]-e0y*vx[0]); c.B0 =  N*e0y; c.C0 = -N*e0x;
    c.A1 = N*(e1x*vy[1]-e1y*vx[1]); c.B1 =  N*e1y; c.C1 = -N*e1x;
    c.A2 = N*(e2x*vy[2]-e2y*vx[2]); c.B2 =  N*e2y; c.C2 = -N*e2x;

    bool inter = true;
    #pragma unroll
    for (int k = 0; k < 4; k++) {
        float cx = (k & 1) ? (float)(RES-1) : 0.0f;
        float cy = (k & 2) ? (float)(RES-1) : 0.0f;
        inter = inter && (fmaf(c.C0, cy, fmaf(c.B0, cx, c.A0)) > 0.0f)
                      && (fmaf(c.C1, cy, fmaf(c.B1, cx, c.A1)) > 0.0f)
                      && (fmaf(c.C2, cy, fmaf(c.B2, cx, c.A2)) > 0.0f);
    }

    float fx0 = fminf(fminf(vx[0],vx[1]),vx[2]) - 1.0f;
    float fx1 = fmaxf(fmaxf(vx[0],vx[1]),vx[2]) + 1.0f;
    float fy0 = fminf(fminf(vy[0],vy[1]),vy[2]) - 1.0f;
    float fy1 = fmaxf(fmaxf(vy[0],vy[1]),vy[2]) + 1.0f;
    bool safe = isfinite(fx0) && isfinite(fx1) && isfinite(fy0) && isfinite(fy1)
                && fabsf(N) > 1e-6f;
    int4 bb;
    if (safe) {
        int x0 = (fx0 < 0.0f) ? 0 : ((fx0 > (float)(RES-1)) ? RES : (int)fx0);
        int x1 = (fx1 > (float)(RES-1)) ? (RES-1) : ((fx1 < 0.0f) ? -1 : (int)fx1);
        int y0 = (fy0 < 0.0f) ? 0 : ((fy0 > (float)(RES-1)) ? RES : (int)fy0);
        int y1 = (fy1 > (float)(RES-1)) ? (RES-1) : ((fy1 < 0.0f) ? -1 : (int)fy1);
        if (x0 > x1 || y0 > y1) { x0 = RES; x1 = -1; y0 = RES; y1 = -1; }
        bb = make_int4(x0, x1, y0, y1);
    } else {
        bb = make_int4(0, RES-1, 0, RES-1);
    }

    // normalized coeffs for the root math (scale-invariant)
    float kap = 0.0f;
    kap = fmaxf(kap, fabsf(c.A0)); kap = fmaxf(kap, 256.0f*fabsf(c.B0)); kap = fmaxf(kap, 256.0f*fabsf(c.C0));
    kap = fmaxf(kap, fabsf(c.A1)); kap = fmaxf(kap, 256.0f*fabsf(c.B1)); kap = fmaxf(kap, 256.0f*fabsf(c.C1));
    kap = fmaxf(kap, fabsf(c.A2)); kap = fmaxf(kap, 256.0f*fabsf(c.B2)); kap = fmaxf(kap, 256.0f*fabsf(c.C2));
    float rk = (kap > 1e-30f) ? (1.0f / kap) : 0.0f;
    Coef n;
    n.A0 = c.A0*rk; n.B0 = c.B0*rk; n.C0 = c.C0*rk;
    n.A1 = c.A1*rk; n.B1 = c.B1*rk; n.C1 = c.C1*rk;
    n.A2 = c.A2*rk; n.B2 = c.B2*rk; n.C2 = c.C2*rk;

    // analytic per-row max, lanes share rows
    float mx = 0.0f;
    for (int y = bb.z + lane; y <= bb.w; y += 32)
        mx = fmaxf(mx, row_max(c, n, bb, y));
    #pragma unroll
    for (int o = 16; o > 0; o >>= 1)
        mx = fmaxf(mx, __shfl_xor_sync(0xffffffffu, mx, o));

    if (lane == 0) {
        float mn = 0.0f;
        if (inter) {   // quasi-concave => grid min at an image corner
            const float e = (float)(RES - 1);
            mn = eval_s(c, 0.0f, 0.0f);
            mn = fminf(mn, eval_s(c, e, 0.0f));
            mn = fminf(mn, eval_s(c, 0.0f, e));
            mn = fminf(mn, eval_s(c, e, e));
        }
        float inv = 1.0f / (mx - mn + EPSF);
        g_q[bt*3+0] = make_float4(c.A0, c.B0, c.C0, c.A1);
        g_q[bt*3+1] = make_float4(c.B1, c.C1, c.A2, c.B2);
        g_q[bt*3+2] = make_float4(c.C2, mn,   inv,  0.0f);
        g_bb[bt]    = bb;
    }
}

// ---------------------------------------------------------------------------
// Kernel 2: pure scatter. grid = (NBT, YSPLIT), 256 threads, no syncs.
// Warp w of split s handles row-pairs k = k0 + s*8 + w, stride 16.
// Per-row intercepts hoisted out of the x loop.
// ---------------------------------------------------------------------------
__global__ void __launch_bounds__(256) scatter_kernel()
{
    const int bt   = blockIdx.x;
    const int b    = bt / NTRI;
    const int wid  = threadIdx.x >> 5;
    const int lane = threadIdx.x & 31;

    const int4   bb = g_bb[bt];
    const int k0 = bb.z >> 1;
    const int k1 = bb.w >> 1;
    const int kstart = k0 + (int)blockIdx.y * 8 + wid;
    if (kstart > k1) return;

    const float4 q0 = g_q[bt*3+0];   // A0 B0 C0 A1
    const float4 q1 = g_q[bt*3+1];   // B1 C1 A2 B2
    const float4 q2 = g_q[bt*3+2];   // C2 mn inv -
    const float mn  = q2.y;
    const float inv = q2.z;

    unsigned long long* __restrict__ acc = g_accum + (size_t)b * NPAIR;
    const float flane = (float)lane;

    for (int k = kstart; k <= k1; k += 8 * YSPLIT) {
        const int   y0 = 2 * k, y1 = 2 * k + 1;
        const float fy0 = (float)y0, fy1 = (float)y1;

        // row intercepts
        const float r00 = fmaf(q0.z, fy0, q0.x), r01 = fmaf(q0.z, fy1, q0.x);
        const float r10 = fmaf(q1.y, fy0, q0.w), r11 = fmaf(q1.y, fy1, q0.w);
        const float r20 = fmaf(q2.x, fy0, q1.z), r21 = fmaf(q2.x, fy1, q1.z);

        float lo0, hi0, lo1, hi1;
        row_iv(q0.y, q1.x, q1.w, r00, r10, r20, lo0, hi0);
        row_iv(q0.y, q1.x, q1.w, r01, r11, r21, lo1, hi1);
        if (y0 < bb.z) { lo0 = 1e30f; hi0 = -1e30f; }
        if (y1 > bb.w) { lo1 = 1e30f; hi1 = -1e30f; }

        float xsf = fmaxf((float)bb.x, ceilf(fminf(lo0, lo1)) - 1.0f);
        float xef = fminf((float)bb.y, floorf(fmaxf(hi0, hi1)) + 1.0f);
        const int xs = (int)xsf;
        const int xe = (int)xef;

        float fx = xsf + flane;
        for (int x = xs + lane; x <= xe; x += 32, fx += 32.0f) {
            // row y0 and row y1 evaluated as independent chains (ILP)
            float u00 = fmaxf(fmaf(q0.y, fx, r00), 0.0f);
            float u01 = fmaxf(fmaf(q0.y, fx, r01), 0.0f);
            float u10 = fmaxf(fmaf(q1.x, fx, r10), 0.0f);
            float u11 = fmaxf(fmaf(q1.x, fx, r11), 0.0f);
            float u20 = fmaxf(fmaf(q1.w, fx, r20), 0.0f);
            float u21 = fmaxf(fmaf(q1.w, fx, r21), 0.0f);
            float d0  = u00 * u10 * u20 - mn;
            float d1  = u01 * u11 * u21 - mn;
            unsigned int v0 = 0u, v1 = 0u;
            if (d0 > 0.0f) v0 = __float2uint_rn(tanh_pade(d0 * inv) * SCALEF);
            if (d1 > 0.0f) v1 = __float2uint_rn(tanh_pade(d1 * inv) * SCALEF);
            unsigned long long p = (unsigned long long)v0
                                 | ((unsigned long long)v1 << 32);
            if (p) atomicAdd(acc + x * (RES / 2) + k, p);
        }
    }
}

// ---------------------------------------------------------------------------
// Kernel 3: unpack fixed point -> float, reset accumulator for next replay.
// ---------------------------------------------------------------------------
__global__ void finalize_kernel(float* __restrict__ out)
{
    const int i = blockIdx.x * blockDim.x + threadIdx.x;
    if (i >= NBATCH * NPAIR) return;
    const unsigned long long p = g_accum[i];
    g_accum[i] = 0ull;
    const int b = i / NPAIR;
    const int r = i - b * NPAIR;          // r = x*128 + k
    const int x = r >> 7;
    const int k = r & 127;
    float* o = out + (size_t)b * NPIX + x * RES + 2 * k;
    o[0] = (float)(unsigned int)(p)       * INVSCALE;
    o[1] = (float)(unsigned int)(p >> 32) * INVSCALE;
}

// ---------------------------------------------------------------------------
extern "C" void kernel_launch(void* const* d_in, const int* in_sizes, int n_in,
                              void* d_out, int out_size)
{
    const float* meshes = (const float*)d_in[0];
    const float* K      = (const float*)d_in[1];
    const int*   idxs   = (const int*)  d_in[2];
    const float* poses  = (const float*)d_in[3];
    float*       out    = (float*)d_out;

    setup_kernel<<<(NBT * 32 + 255) / 256, 256>>>(meshes, K, idxs, poses);

    dim3 g(NBT, YSPLIT);
    scatter_kernel<<<g, 256>>>();

    finalize_kernel<<<(NBATCH * NPAIR + 255) / 256, 256>>>(out);
}